// round 12
// baseline (speedup 1.0000x reference)
#include <cuda_runtime.h>
#include <cuda_bf16.h>
#include <math.h>
#include <stdint.h>

#define NB 4
#define NH 16
#define NS 1024
#define ND 64
#define TQ 32
#define TK 64
#define NTILES (NS / TK)

#define QHS 68      // q packed tile stride (words), mod 32 == 4
#define KHS 68      // k tile stride (words), mod 32 == 4
#define VSS 72      // v tile stride, mod 32 == 8
#define EBS 68      // e tile stride (kernel B), mod 32 == 4
#define PRS 66      // reduction scratch stride

// Precomputed, head-independent tables + scratch.
__device__ float    g_resc[NB * NS * NS];        // (1+e)/(1+exp(1-dist))
__device__ float    g_madj[NB * NS * NS];        // mask ? adj : -1e9
__device__ uint32_t g_qhl[NB * NH * NS * ND];    // q/8 packed bf16 hi|lo
__device__ uint32_t g_khl[NB * NH * NS * ND];    // k packed bf16 hi|lo
__device__ float    g_vtf[NB * NH * NS * ND];    // tf32(v) bits
__device__ float    g_rinv[NB * NH * NS];        // 1 / row sums

__global__ void prep_kernel(const float* __restrict__ dist,
                            const float* __restrict__ adj,
                            const int*   __restrict__ mask) {
    int i = (blockIdx.x * blockDim.x + threadIdx.x) * 4;
    int b = i >> 20;
    int j = i & (NS - 1);
    float4 d = *(const float4*)(dist + i);
    float4 a = *(const float4*)(adj + i);
    int4   m = *(const int4*)(mask + b * NS + j);
    float4 r;
    r.x = 3.7182817f / (1.0f + __expf(1.0f - d.x));
    r.y = 3.7182817f / (1.0f + __expf(1.0f - d.y));
    r.z = 3.7182817f / (1.0f + __expf(1.0f - d.z));
    r.w = 3.7182817f / (1.0f + __expf(1.0f - d.w));
    *(float4*)(g_resc + i) = r;
    float4 ma;
    ma.x = (m.x == 0) ? -1.0e9f : a.x;
    ma.y = (m.y == 0) ? -1.0e9f : a.y;
    ma.z = (m.z == 0) ? -1.0e9f : a.z;
    ma.w = (m.w == 0) ? -1.0e9f : a.w;
    *(float4*)(g_madj + i) = ma;
}

__device__ __forceinline__ uint32_t f2tf(float f) {
    uint32_t r;
    asm("cvt.rna.tf32.f32 %0, %1;" : "=r"(r) : "f"(f));
    return r;
}
__device__ __forceinline__ uint32_t pack_bf16x2_split(float f) {
    __nv_bfloat16 h = __float2bfloat16(f);
    float resid = f - __bfloat162float(h);
    __nv_bfloat16 l = __float2bfloat16(resid);
    return (uint32_t)__bfloat16_as_ushort(h) |
           ((uint32_t)__bfloat16_as_ushort(l) << 16);
}

__global__ void prep_qkv_kernel(const float* __restrict__ q,
                                const float* __restrict__ k,
                                const float* __restrict__ v) {
    int i = (blockIdx.x * blockDim.x + threadIdx.x) * 4;
    float4 qv = *(const float4*)(q + i);
    float4 kv = *(const float4*)(k + i);
    float4 vv = *(const float4*)(v + i);
    uint4 qo, ko;
    float4 vo;
    qo.x = pack_bf16x2_split(qv.x * 0.125f);
    qo.y = pack_bf16x2_split(qv.y * 0.125f);
    qo.z = pack_bf16x2_split(qv.z * 0.125f);
    qo.w = pack_bf16x2_split(qv.w * 0.125f);
    ko.x = pack_bf16x2_split(kv.x);
    ko.y = pack_bf16x2_split(kv.y);
    ko.z = pack_bf16x2_split(kv.z);
    ko.w = pack_bf16x2_split(kv.w);
    vo.x = __uint_as_float(f2tf(vv.x));
    vo.y = __uint_as_float(f2tf(vv.y));
    vo.z = __uint_as_float(f2tf(vv.z));
    vo.w = __uint_as_float(f2tf(vv.w));
    *(uint4*)(g_qhl + i) = qo;
    *(uint4*)(g_khl + i) = ko;
    *(float4*)(g_vtf + i) = vo;
}

__device__ __forceinline__ void mma_bf16(float* c,
                                         uint32_t a0, uint32_t a1, uint32_t a2, uint32_t a3,
                                         uint32_t b0, uint32_t b1) {
    asm volatile("mma.sync.aligned.m16n8k16.row.col.f32.bf16.bf16.f32 "
                 "{%0,%1,%2,%3}, {%4,%5,%6,%7}, {%8,%9}, {%0,%1,%2,%3};"
                 : "+f"(c[0]), "+f"(c[1]), "+f"(c[2]), "+f"(c[3])
                 : "r"(a0), "r"(a1), "r"(a2), "r"(a3), "r"(b0), "r"(b1));
}
__device__ __forceinline__ void mma_tf32(float* c,
                                         uint32_t a0, uint32_t a1, uint32_t a2, uint32_t a3,
                                         uint32_t b0, uint32_t b1) {
    asm volatile("mma.sync.aligned.m16n8k8.row.col.f32.tf32.tf32.f32 "
                 "{%0,%1,%2,%3}, {%4,%5,%6,%7}, {%8,%9}, {%0,%1,%2,%3};"
                 : "+f"(c[0]), "+f"(c[1]), "+f"(c[2]), "+f"(c[3])
                 : "r"(a0), "r"(a1), "r"(a2), "r"(a3), "r"(b0), "r"(b1));
}

__device__ __forceinline__ void cp_async16(void* smem_dst, const void* gsrc) {
    uint32_t sa = (uint32_t)__cvta_generic_to_shared(smem_dst);
    asm volatile("cp.async.cg.shared.global [%0], [%1], 16;" :: "r"(sa), "l"(gsrc));
}
#define CP_COMMIT()  asm volatile("cp.async.commit_group;")
#define CP_WAIT(n)   asm volatile("cp.async.wait_group %0;" :: "n"(n))

// ============ Kernel A: scores -> unnormalized e (tf32 bits) ============
#define ANT 256
__global__ __launch_bounds__(ANT, 3)
void score_kernel(float* __restrict__ attn_out) {
    extern __shared__ float smem[];
    uint32_t* qhl_s = (uint32_t*)smem;                 // TQ*QHS (2176 w)
    uint32_t* kbuf  = (uint32_t*)(smem + TQ * QHS);    // 2*TK*KHS (8704 w)
    float*    rs_sm = smem + TQ * QHS + 2 * TK * KHS;  // 32

    const int tid  = threadIdx.x;
    const int wid  = tid >> 5;
    const int lane = tid & 31;
    const int g    = lane >> 2;
    const int tg   = lane & 3;
    const int wm   = wid >> 2;    // 0..1
    const int wn   = wid & 3;     // 0..3 (n16 group within TK=64)

    const int q0 = blockIdx.x * TQ;
    const int h  = blockIdx.y;
    const int b  = blockIdx.z;
    const size_t bh = (size_t)b * NH + h;

    const uint32_t* qg  = g_qhl + (bh * NS + q0) * ND;
    const uint32_t* khg = g_khl + bh * NS * ND;
    float* eg = attn_out + (bh * NS + q0) * NS;

    if (tid < 32) rs_sm[tid] = 0.0f;

    // ---- prologue: q + k0 (group 0), k1 (group 1) ----
    for (int i = tid; i < TQ * 16; i += ANT) {
        int r = i >> 4, c = (i & 15) << 2;
        cp_async16(qhl_s + r * QHS + c, qg + (size_t)r * ND + c);
    }
    for (int i = tid; i < TK * 16; i += ANT) {
        int r = i >> 4, c = (i & 15) << 2;
        cp_async16(kbuf + r * KHS + c, khg + (size_t)r * ND + c);
    }
    CP_COMMIT();
    for (int i = tid; i < TK * 16; i += ANT) {
        int r = i >> 4, c = (i & 15) << 2;
        cp_async16(kbuf + TK * KHS + r * KHS + c, khg + (size_t)(TK + r) * ND + c);
    }
    CP_COMMIT();
    CP_WAIT(1);
    __syncthreads();

    const int r_lo = wm * 16 + g;
    float rs0 = 0.0f, rs1 = 0.0f;
    const float* rbase = g_resc + ((size_t)b * NS + q0 + r_lo) * NS;
    const float* abase = g_madj + ((size_t)b * NS + q0 + r_lo) * NS;

    for (int kt = 0; kt < NTILES; kt++) {
        if (kt < NTILES - 1) { CP_WAIT(1); } else { CP_WAIT(0); }
        __syncthreads();

        const uint32_t* kw = kbuf + (kt & 1) * TK * KHS;

        float chh[2][4], cll[2][4];
        #pragma unroll
        for (int nt = 0; nt < 2; nt++)
            #pragma unroll
            for (int j = 0; j < 4; j++) { chh[nt][j] = 0.0f; cll[nt][j] = 0.0f; }

        #pragma unroll
        for (int ks = 0; ks < 8; ks++) {
            int col = ks * 8 + tg;
            uint32_t p0 = qhl_s[r_lo * QHS + col];
            uint32_t p1 = qhl_s[(r_lo + 8) * QHS + col];
            uint32_t p2 = qhl_s[r_lo * QHS + col + 4];
            uint32_t p3 = qhl_s[(r_lo + 8) * QHS + col + 4];
            uint32_t hh0 = __byte_perm(p0, p0, 0x1010);
            uint32_t hh1 = __byte_perm(p1, p1, 0x1010);
            uint32_t hh2 = __byte_perm(p2, p2, 0x1010);
            uint32_t hh3 = __byte_perm(p3, p3, 0x1010);
            uint32_t ll0 = __byte_perm(p0, p0, 0x3232);
            uint32_t ll1 = __byte_perm(p1, p1, 0x3232);
            uint32_t ll2 = __byte_perm(p2, p2, 0x3232);
            uint32_t ll3 = __byte_perm(p3, p3, 0x3232);
            #pragma unroll
            for (int nt = 0; nt < 2; nt++) {
                uint32_t bp0 = kw[(wn * 16 + nt * 8 + g) * KHS + col];
                uint32_t bp1 = kw[(wn * 16 + nt * 8 + g) * KHS + col + 4];
                mma_bf16(chh[nt], hh0, hh1, hh2, hh3, bp0, bp1);
                mma_bf16(cll[nt], ll0, ll1, ll2, ll3, bp0, bp1);
            }
        }

        // epilogue: e = exp(relu(s)*resc + madj); row sums; store tf32(e)
        #pragma unroll
        for (int nt = 0; nt < 2; nt++) {
            int kc = kt * TK + wn * 16 + nt * 8 + 2 * tg;
            float2 rl = *(const float2*)(rbase + kc);
            float2 al = *(const float2*)(abase + kc);
            float2 rh = *(const float2*)(rbase + 8 * NS + kc);
            float2 ah = *(const float2*)(abase + 8 * NS + kc);
            float e00 = __expf(fmaxf(chh[nt][0] + cll[nt][0], 0.0f) * rl.x + al.x);
            float e01 = __expf(fmaxf(chh[nt][1] + cll[nt][1], 0.0f) * rl.y + al.y);
            float e10 = __expf(fmaxf(chh[nt][2] + cll[nt][2], 0.0f) * rh.x + ah.x);
            float e11 = __expf(fmaxf(chh[nt][3] + cll[nt][3], 0.0f) * rh.y + ah.y);
            rs0 += e00 + e01;
            rs1 += e10 + e11;
            float2 t0 = make_float2(__uint_as_float(f2tf(e00)), __uint_as_float(f2tf(e01)));
            float2 t1 = make_float2(__uint_as_float(f2tf(e10)), __uint_as_float(f2tf(e11)));
            __stcs((float2*)(eg + (size_t)r_lo * NS + kc), t0);
            __stcs((float2*)(eg + (size_t)(r_lo + 8) * NS + kc), t1);
        }
        __syncthreads();

        if (kt + 2 < NTILES) {
            uint32_t* dst = kbuf + (kt & 1) * TK * KHS;
            for (int i = tid; i < TK * 16; i += ANT) {
                int r = i >> 4, c = (i & 15) << 2;
                cp_async16(dst + r * KHS + c,
                           khg + (size_t)((kt + 2) * TK + r) * ND + c);
            }
            CP_COMMIT();
        }
    }

    // row sums -> g_rinv
    rs0 += __shfl_xor_sync(0xffffffffu, rs0, 1);
    rs0 += __shfl_xor_sync(0xffffffffu, rs0, 2);
    rs1 += __shfl_xor_sync(0xffffffffu, rs1, 1);
    rs1 += __shfl_xor_sync(0xffffffffu, rs1, 2);
    if (tg == 0) {
        atomicAdd(&rs_sm[r_lo], rs0);
        atomicAdd(&rs_sm[r_lo + 8], rs1);
    }
    __syncthreads();
    if (tid < 32) g_rinv[bh * NS + q0 + tid] = 1.0f / rs_sm[tid];
}

// ============ Kernel B: normalize attn in place + out = P @ V ============
#define BNT 256
__global__ __launch_bounds__(BNT, 3)
void pv_kernel(float* __restrict__ out,
               float* __restrict__ attn) {
    extern __shared__ float smem[];
    float* ebuf   = smem;                              // 2*TQ*EBS (4352 w)
    float* vbuf   = ebuf + 2 * TQ * EBS;               // 2*TK*VSS (9216 w)
    float* rinv_s = vbuf + 2 * TK * VSS;               // 32
    float* scratch = vbuf;                             // dead after tile loop

    const int tid  = threadIdx.x;
    const int wid  = tid >> 5;
    const int lane = tid & 31;
    const int g    = lane >> 2;
    const int tg   = lane & 3;
    const int wm   = wid >> 2;    // 0..1 (m16)
    const int wk   = wid & 3;     // 0..3 (k16 slice within TK=64)

    const int q0 = blockIdx.x * TQ;
    const int h  = blockIdx.y;
    const int b  = blockIdx.z;
    const size_t bh = (size_t)b * NH + h;

    float* eg = attn + (bh * NS + q0) * NS;
    const float* vg = g_vtf + bh * NS * ND;

    if (tid < 32) rinv_s[tid] = g_rinv[bh * NS + q0 + tid];

    // ---- prologue: tiles 0,1 (e + v), one cp group each ----
    for (int t = 0; t < 2; t++) {
        float* ed = ebuf + t * TQ * EBS;
        float* vd = vbuf + t * TK * VSS;
        for (int i = tid; i < TQ * (TK / 4); i += BNT) {
            int r = i >> 4, c = (i & 15) << 2;
            cp_async16(ed + r * EBS + c, eg + (size_t)r * NS + t * TK + c);
        }
        for (int i = tid; i < TK * 16; i += BNT) {
            int r = i >> 4, c = (i & 15) << 2;
            cp_async16(vd + r * VSS + c, vg + (size_t)(t * TK + r) * ND + c);
        }
        CP_COMMIT();
    }
    CP_WAIT(1);
    __syncthreads();

    const int r_lo = wm * 16 + g;
    float acc[8][4];
    #pragma unroll
    for (int nt = 0; nt < 8; nt++)
        #pragma unroll
        for (int j = 0; j < 4; j++) acc[nt][j] = 0.0f;

    for (int vt = 0; vt < NTILES; vt++) {
        if (vt < NTILES - 1) { CP_WAIT(1); } else { CP_WAIT(0); }
        __syncthreads();

        const float* eb = ebuf + (vt & 1) * TQ * EBS;
        const float* vb = vbuf + (vt & 1) * TK * VSS;

        #pragma unroll
        for (int s = 0; s < 2; s++) {
            int kl = wk * 16 + s * 8;
            uint32_t a0 = __float_as_uint(eb[r_lo * EBS + kl + tg]);
            uint32_t a1 = __float_as_uint(eb[(r_lo + 8) * EBS + kl + tg]);
            uint32_t a2 = __float_as_uint(eb[r_lo * EBS + kl + tg + 4]);
            uint32_t a3 = __float_as_uint(eb[(r_lo + 8) * EBS + kl + tg + 4]);
            #pragma unroll
            for (int nt = 0; nt < 8; nt++) {
                uint32_t b0 = __float_as_uint(vb[(kl + tg) * VSS + nt * 8 + g]);
                uint32_t b1 = __float_as_uint(vb[(kl + tg + 4) * VSS + nt * 8 + g]);
                mma_tf32(acc[nt], a0, a1, a2, a3, b0, b1);
            }
        }

        // normalize + write back attn chunk [TQ x TK]
        for (int i = tid; i < TQ * (TK / 4); i += BNT) {
            int row = i >> 4, c = (i & 15) << 2;
            float rv = rinv_s[row];
            float4 p = *(const float4*)(eb + row * EBS + c);
            p.x *= rv; p.y *= rv; p.z *= rv; p.w *= rv;
            __stcs((float4*)(eg + (size_t)row * NS + vt * TK + c), p);
        }
        __syncthreads();

        if (vt + 2 < NTILES) {
            float* ed = ebuf + (vt & 1) * TQ * EBS;
            float* vd = vbuf + (vt & 1) * TK * VSS;
            for (int i = tid; i < TQ * (TK / 4); i += BNT) {
                int r = i >> 4, c = (i & 15) << 2;
                cp_async16(ed + r * EBS + c, eg + (size_t)r * NS + (vt + 2) * TK + c);
            }
            for (int i = tid; i < TK * 16; i += BNT) {
                int r = i >> 4, c = (i & 15) << 2;
                cp_async16(vd + r * VSS + c, vg + (size_t)((vt + 2) * TK + r) * ND + c);
            }
            CP_COMMIT();
        }
    }

    // ---- reduce 4 k-partials via scratch (dead vbuf) ----
    {
        float* reg = scratch + (wk * TQ) * PRS;
        #pragma unroll
        for (int nt = 0; nt < 8; nt++) {
            *(float2*)(reg + (wm * 16 + g) * PRS + nt * 8 + 2 * tg) = make_float2(acc[nt][0], acc[nt][1]);
            *(float2*)(reg + (wm * 16 + g + 8) * PRS + nt * 8 + 2 * tg) = make_float2(acc[nt][2], acc[nt][3]);
        }
    }
    __syncthreads();
    {
        int row = tid >> 3;            // 0..31
        int c8  = (tid & 7) << 3;      // 0..56, 8 cols each
        float s[8];
        #pragma unroll
        for (int j = 0; j < 8; j++) s[j] = 0.0f;
        #pragma unroll
        for (int k = 0; k < 4; k++) {
            const float* p = scratch + (k * TQ + row) * PRS + c8;
            #pragma unroll
            for (int j = 0; j < 8; j++) s[j] += p[j];
        }
        float rv = rinv_s[row];
        float4 o0 = make_float4(s[0] * rv, s[1] * rv, s[2] * rv, s[3] * rv);
        float4 o1 = make_float4(s[4] * rv, s[5] * rv, s[6] * rv, s[7] * rv);
        float* op = out + (bh * NS + (size_t)(q0 + row)) * ND + c8;
        *(float4*)op = o0;
        *(float4*)(op + 4) = o1;
    }
}

extern "C" void kernel_launch(void* const* d_in, const int* in_sizes, int n_in,
                              void* d_out, int out_size) {
    const float* q    = (const float*)d_in[0];
    const float* k    = (const float*)d_in[1];
    const float* v    = (const float*)d_in[2];
    const int*   mask = (const int*)  d_in[3];
    const float* adj  = (const float*)d_in[4];
    const float* dist = (const float*)d_in[5];

    float* out  = (float*)d_out;                      // [B,H,S,D]
    float* attn = out + (size_t)NB * NH * NS * ND;    // [B,H,S,S]

    prep_kernel<<<(NB * NS * NS) / 1024, 256>>>(dist, adj, mask);
    prep_qkv_kernel<<<(NB * NH * NS * ND) / 1024, 256>>>(q, k, v);

    dim3 grid(NS / TQ, NH, NB);

    const size_t smem_a = (size_t)(TQ * QHS + 2 * TK * KHS + 32) * sizeof(float);
    cudaFuncSetAttribute(score_kernel,
                         cudaFuncAttributeMaxDynamicSharedMemorySize, (int)smem_a);
    score_kernel<<<grid, ANT, smem_a>>>(attn);

    const size_t smem_b = (size_t)(2 * TQ * EBS + 2 * TK * VSS + 32) * sizeof(float);
    cudaFuncSetAttribute(pv_kernel,
                         cudaFuncAttributeMaxDynamicSharedMemorySize, (int)smem_b);
    pv_kernel<<<grid, BNT, smem_b>>>(out, attn);
}

// round 13
// speedup vs baseline: 1.1326x; 1.1326x over previous
#include <cuda_runtime.h>
#include <cuda_bf16.h>
#include <math.h>
#include <stdint.h>

#define NB 4
#define NH 16
#define NS 1024
#define ND 64

#define QHS 68      // q packed tile stride (words), mod 32 == 4
#define KHS 68      // k tile stride (words), mod 32 == 4
#define VSS 72      // v tile stride, mod 32 == 8
#define EBS 68      // e tile stride (kernel B), mod 32 == 4
#define PRS 66      // reduction scratch stride

// Kernel A geometry
#define ATQ 64
#define ATK 128
#define ANT 512
#define ANTILES (NS / ATK)

// Kernel B geometry
#define BTQ 32
#define BTK 64
#define BNT 256
#define BNTILES (NS / BTK)

// Precomputed, head-independent tables + scratch.
__device__ float    g_resc[NB * NS * NS];        // (1+e)/(1+exp(1-dist))
__device__ float    g_madj[NB * NS * NS];        // mask ? adj : -1e9
__device__ uint32_t g_qhl[NB * NH * NS * ND];    // q/8 packed bf16 hi|lo
__device__ uint32_t g_khl[NB * NH * NS * ND];    // k packed bf16 hi|lo
__device__ float    g_vtf[NB * NH * NS * ND];    // tf32(v) bits
__device__ float    g_rinv[NB * NH * NS];        // 1 / row sums

__global__ void prep_kernel(const float* __restrict__ dist,
                            const float* __restrict__ adj,
                            const int*   __restrict__ mask) {
    int i = (blockIdx.x * blockDim.x + threadIdx.x) * 4;
    int b = i >> 20;
    int j = i & (NS - 1);
    float4 d = *(const float4*)(dist + i);
    float4 a = *(const float4*)(adj + i);
    int4   m = *(const int4*)(mask + b * NS + j);
    float4 r;
    r.x = 3.7182817f / (1.0f + __expf(1.0f - d.x));
    r.y = 3.7182817f / (1.0f + __expf(1.0f - d.y));
    r.z = 3.7182817f / (1.0f + __expf(1.0f - d.z));
    r.w = 3.7182817f / (1.0f + __expf(1.0f - d.w));
    *(float4*)(g_resc + i) = r;
    float4 ma;
    ma.x = (m.x == 0) ? -1.0e9f : a.x;
    ma.y = (m.y == 0) ? -1.0e9f : a.y;
    ma.z = (m.z == 0) ? -1.0e9f : a.z;
    ma.w = (m.w == 0) ? -1.0e9f : a.w;
    *(float4*)(g_madj + i) = ma;
}

__device__ __forceinline__ uint32_t f2tf(float f) {
    uint32_t r;
    asm("cvt.rna.tf32.f32 %0, %1;" : "=r"(r) : "f"(f));
    return r;
}
__device__ __forceinline__ uint32_t pack_bf16x2_split(float f) {
    __nv_bfloat16 h = __float2bfloat16(f);
    float resid = f - __bfloat162float(h);
    __nv_bfloat16 l = __float2bfloat16(resid);
    return (uint32_t)__bfloat16_as_ushort(h) |
           ((uint32_t)__bfloat16_as_ushort(l) << 16);
}

__global__ void prep_qkv_kernel(const float* __restrict__ q,
                                const float* __restrict__ k,
                                const float* __restrict__ v) {
    int i = (blockIdx.x * blockDim.x + threadIdx.x) * 4;
    float4 qv = *(const float4*)(q + i);
    float4 kv = *(const float4*)(k + i);
    float4 vv = *(const float4*)(v + i);
    uint4 qo, ko;
    float4 vo;
    qo.x = pack_bf16x2_split(qv.x * 0.125f);
    qo.y = pack_bf16x2_split(qv.y * 0.125f);
    qo.z = pack_bf16x2_split(qv.z * 0.125f);
    qo.w = pack_bf16x2_split(qv.w * 0.125f);
    ko.x = pack_bf16x2_split(kv.x);
    ko.y = pack_bf16x2_split(kv.y);
    ko.z = pack_bf16x2_split(kv.z);
    ko.w = pack_bf16x2_split(kv.w);
    vo.x = __uint_as_float(f2tf(vv.x));
    vo.y = __uint_as_float(f2tf(vv.y));
    vo.z = __uint_as_float(f2tf(vv.z));
    vo.w = __uint_as_float(f2tf(vv.w));
    *(uint4*)(g_qhl + i) = qo;
    *(uint4*)(g_khl + i) = ko;
    *(float4*)(g_vtf + i) = vo;
}

__device__ __forceinline__ void mma_bf16(float* c,
                                         uint32_t a0, uint32_t a1, uint32_t a2, uint32_t a3,
                                         uint32_t b0, uint32_t b1) {
    asm volatile("mma.sync.aligned.m16n8k16.row.col.f32.bf16.bf16.f32 "
                 "{%0,%1,%2,%3}, {%4,%5,%6,%7}, {%8,%9}, {%0,%1,%2,%3};"
                 : "+f"(c[0]), "+f"(c[1]), "+f"(c[2]), "+f"(c[3])
                 : "r"(a0), "r"(a1), "r"(a2), "r"(a3), "r"(b0), "r"(b1));
}
__device__ __forceinline__ void mma_tf32(float* c,
                                         uint32_t a0, uint32_t a1, uint32_t a2, uint32_t a3,
                                         uint32_t b0, uint32_t b1) {
    asm volatile("mma.sync.aligned.m16n8k8.row.col.f32.tf32.tf32.f32 "
                 "{%0,%1,%2,%3}, {%4,%5,%6,%7}, {%8,%9}, {%0,%1,%2,%3};"
                 : "+f"(c[0]), "+f"(c[1]), "+f"(c[2]), "+f"(c[3])
                 : "r"(a0), "r"(a1), "r"(a2), "r"(a3), "r"(b0), "r"(b1));
}

__device__ __forceinline__ void cp_async16(void* smem_dst, const void* gsrc) {
    uint32_t sa = (uint32_t)__cvta_generic_to_shared(smem_dst);
    asm volatile("cp.async.cg.shared.global [%0], [%1], 16;" :: "r"(sa), "l"(gsrc));
}
#define CP_COMMIT()  asm volatile("cp.async.commit_group;")
#define CP_WAIT(n)   asm volatile("cp.async.wait_group %0;" :: "n"(n))

// ============ Kernel A: scores -> unnormalized e (tf32 bits), TQ=64 ============
__global__ __launch_bounds__(ANT, 1)
void score_kernel(float* __restrict__ attn_out) {
    extern __shared__ float smem[];
    uint32_t* qhl_s = (uint32_t*)smem;                   // ATQ*QHS   (4352 w)
    uint32_t* kbuf  = (uint32_t*)(smem + ATQ * QHS);     // 2*ATK*KHS (17408 w)
    float*    rs_sm = smem + ATQ * QHS + 2 * ATK * KHS;  // 64

    const int tid  = threadIdx.x;
    const int wid  = tid >> 5;
    const int lane = tid & 31;
    const int g    = lane >> 2;
    const int tg   = lane & 3;
    const int wm   = wid >> 2;    // 0..3 (m16 group within TQ=64)
    const int wn   = wid & 3;     // 0..3 (n32 group within TK=128)

    const int q0 = blockIdx.x * ATQ;
    const int h  = blockIdx.y;
    const int b  = blockIdx.z;
    const size_t bh = (size_t)b * NH + h;

    const uint32_t* qg  = g_qhl + (bh * NS + q0) * ND;
    const uint32_t* khg = g_khl + bh * NS * ND;
    float* eg = attn_out + (bh * NS + q0) * NS;

    if (tid < 64) rs_sm[tid] = 0.0f;

    // ---- prologue: q + k0 (group 0), k1 (group 1) ----
    for (int i = tid; i < ATQ * 16; i += ANT) {
        int r = i >> 4, c = (i & 15) << 2;
        cp_async16(qhl_s + r * QHS + c, qg + (size_t)r * ND + c);
    }
    for (int i = tid; i < ATK * 16; i += ANT) {
        int r = i >> 4, c = (i & 15) << 2;
        cp_async16(kbuf + r * KHS + c, khg + (size_t)r * ND + c);
    }
    CP_COMMIT();
    for (int i = tid; i < ATK * 16; i += ANT) {
        int r = i >> 4, c = (i & 15) << 2;
        cp_async16(kbuf + ATK * KHS + r * KHS + c, khg + (size_t)(ATK + r) * ND + c);
    }
    CP_COMMIT();
    CP_WAIT(1);
    __syncthreads();

    // ---- A fragments (m16 slice of q) -> packed regs ----
    uint32_t apk[8][4];
    const int r_lo = wm * 16 + g;
    #pragma unroll
    for (int ks = 0; ks < 8; ks++) {
        int col = ks * 8 + tg;
        apk[ks][0] = qhl_s[r_lo * QHS + col];
        apk[ks][1] = qhl_s[(r_lo + 8) * QHS + col];
        apk[ks][2] = qhl_s[r_lo * QHS + col + 4];
        apk[ks][3] = qhl_s[(r_lo + 8) * QHS + col + 4];
    }

    float rs0 = 0.0f, rs1 = 0.0f;
    const float* rbase = g_resc + ((size_t)b * NS + q0 + r_lo) * NS;
    const float* abase = g_madj + ((size_t)b * NS + q0 + r_lo) * NS;

    for (int kt = 0; kt < ANTILES; kt++) {
        if (kt < ANTILES - 1) { CP_WAIT(1); } else { CP_WAIT(0); }
        __syncthreads();

        const uint32_t* kw = kbuf + (kt & 1) * ATK * KHS;

        float chh[4][4], cll[4][4];
        #pragma unroll
        for (int nt = 0; nt < 4; nt++)
            #pragma unroll
            for (int j = 0; j < 4; j++) { chh[nt][j] = 0.0f; cll[nt][j] = 0.0f; }

        #pragma unroll
        for (int ks = 0; ks < 8; ks++) {
            int col = ks * 8 + tg;
            uint32_t p0 = apk[ks][0], p1 = apk[ks][1];
            uint32_t p2 = apk[ks][2], p3 = apk[ks][3];
            uint32_t hh0 = __byte_perm(p0, p0, 0x1010);
            uint32_t hh1 = __byte_perm(p1, p1, 0x1010);
            uint32_t hh2 = __byte_perm(p2, p2, 0x1010);
            uint32_t hh3 = __byte_perm(p3, p3, 0x1010);
            uint32_t ll0 = __byte_perm(p0, p0, 0x3232);
            uint32_t ll1 = __byte_perm(p1, p1, 0x3232);
            uint32_t ll2 = __byte_perm(p2, p2, 0x3232);
            uint32_t ll3 = __byte_perm(p3, p3, 0x3232);
            #pragma unroll
            for (int nt = 0; nt < 4; nt++) {
                uint32_t bp0 = kw[(wn * 32 + nt * 8 + g) * KHS + col];
                uint32_t bp1 = kw[(wn * 32 + nt * 8 + g) * KHS + col + 4];
                mma_bf16(chh[nt], hh0, hh1, hh2, hh3, bp0, bp1);
                mma_bf16(cll[nt], ll0, ll1, ll2, ll3, bp0, bp1);
            }
        }

        // epilogue: e = exp(relu(s)*resc + madj); row sums; store tf32(e)
        #pragma unroll
        for (int nt = 0; nt < 4; nt++) {
            int kc = kt * ATK + wn * 32 + nt * 8 + 2 * tg;
            float2 rl = *(const float2*)(rbase + kc);
            float2 al = *(const float2*)(abase + kc);
            float2 rh = *(const float2*)(rbase + 8 * NS + kc);
            float2 ah = *(const float2*)(abase + 8 * NS + kc);
            float e00 = __expf(fmaxf(chh[nt][0] + cll[nt][0], 0.0f) * rl.x + al.x);
            float e01 = __expf(fmaxf(chh[nt][1] + cll[nt][1], 0.0f) * rl.y + al.y);
            float e10 = __expf(fmaxf(chh[nt][2] + cll[nt][2], 0.0f) * rh.x + ah.x);
            float e11 = __expf(fmaxf(chh[nt][3] + cll[nt][3], 0.0f) * rh.y + ah.y);
            rs0 += e00 + e01;
            rs1 += e10 + e11;
            float2 t0 = make_float2(__uint_as_float(f2tf(e00)), __uint_as_float(f2tf(e01)));
            float2 t1 = make_float2(__uint_as_float(f2tf(e10)), __uint_as_float(f2tf(e11)));
            __stcs((float2*)(eg + (size_t)r_lo * NS + kc), t0);
            __stcs((float2*)(eg + (size_t)(r_lo + 8) * NS + kc), t1);
        }
        __syncthreads();

        if (kt + 2 < ANTILES) {
            uint32_t* dst = kbuf + (kt & 1) * ATK * KHS;
            for (int i = tid; i < ATK * 16; i += ANT) {
                int r = i >> 4, c = (i & 15) << 2;
                cp_async16(dst + r * KHS + c,
                           khg + (size_t)((kt + 2) * ATK + r) * ND + c);
            }
            CP_COMMIT();
        }
    }

    // row sums -> g_rinv
    rs0 += __shfl_xor_sync(0xffffffffu, rs0, 1);
    rs0 += __shfl_xor_sync(0xffffffffu, rs0, 2);
    rs1 += __shfl_xor_sync(0xffffffffu, rs1, 1);
    rs1 += __shfl_xor_sync(0xffffffffu, rs1, 2);
    if (tg == 0) {
        atomicAdd(&rs_sm[r_lo], rs0);
        atomicAdd(&rs_sm[r_lo + 8], rs1);
    }
    __syncthreads();
    if (tid < 64) g_rinv[bh * NS + q0 + tid] = 1.0f / rs_sm[tid];
}

// ============ Kernel B: normalize attn in place + out = P @ V ============
__global__ __launch_bounds__(BNT, 3)
void pv_kernel(float* __restrict__ out,
               float* __restrict__ attn) {
    extern __shared__ float smem[];
    float* ebuf   = smem;                              // 2*BTQ*EBS (4352 w)
    float* vbuf   = ebuf + 2 * BTQ * EBS;              // 2*BTK*VSS (9216 w)
    float* rinv_s = vbuf + 2 * BTK * VSS;              // 32
    float* scratch = vbuf;                             // dead after tile loop

    const int tid  = threadIdx.x;
    const int wid  = tid >> 5;
    const int lane = tid & 31;
    const int g    = lane >> 2;
    const int tg   = lane & 3;
    const int wm   = wid >> 2;    // 0..1 (m16)
    const int wk   = wid & 3;     // 0..3 (k16 slice within BTK=64)

    const int q0 = blockIdx.x * BTQ;
    const int h  = blockIdx.y;
    const int b  = blockIdx.z;
    const size_t bh = (size_t)b * NH + h;

    float* eg = attn + (bh * NS + q0) * NS;
    const float* vg = g_vtf + bh * NS * ND;

    if (tid < 32) rinv_s[tid] = g_rinv[bh * NS + q0 + tid];

    // ---- prologue: tiles 0,1 (e + v), one cp group each ----
    for (int t = 0; t < 2; t++) {
        float* ed = ebuf + t * BTQ * EBS;
        float* vd = vbuf + t * BTK * VSS;
        for (int i = tid; i < BTQ * (BTK / 4); i += BNT) {
            int r = i >> 4, c = (i & 15) << 2;
            cp_async16(ed + r * EBS + c, eg + (size_t)r * NS + t * BTK + c);
        }
        for (int i = tid; i < BTK * 16; i += BNT) {
            int r = i >> 4, c = (i & 15) << 2;
            cp_async16(vd + r * VSS + c, vg + (size_t)(t * BTK + r) * ND + c);
        }
        CP_COMMIT();
    }
    CP_WAIT(1);
    __syncthreads();

    const int r_lo = wm * 16 + g;
    float acc[8][4];
    #pragma unroll
    for (int nt = 0; nt < 8; nt++)
        #pragma unroll
        for (int j = 0; j < 4; j++) acc[nt][j] = 0.0f;

    for (int vt = 0; vt < BNTILES; vt++) {
        if (vt < BNTILES - 1) { CP_WAIT(1); } else { CP_WAIT(0); }
        __syncthreads();

        const float* eb = ebuf + (vt & 1) * BTQ * EBS;
        const float* vb = vbuf + (vt & 1) * BTK * VSS;

        #pragma unroll
        for (int s = 0; s < 2; s++) {
            int kl = wk * 16 + s * 8;
            uint32_t a0 = __float_as_uint(eb[r_lo * EBS + kl + tg]);
            uint32_t a1 = __float_as_uint(eb[(r_lo + 8) * EBS + kl + tg]);
            uint32_t a2 = __float_as_uint(eb[r_lo * EBS + kl + tg + 4]);
            uint32_t a3 = __float_as_uint(eb[(r_lo + 8) * EBS + kl + tg + 4]);
            #pragma unroll
            for (int nt = 0; nt < 8; nt++) {
                uint32_t b0 = __float_as_uint(vb[(kl + tg) * VSS + nt * 8 + g]);
                uint32_t b1 = __float_as_uint(vb[(kl + tg + 4) * VSS + nt * 8 + g]);
                mma_tf32(acc[nt], a0, a1, a2, a3, b0, b1);
            }
        }

        // normalize + write back attn chunk [BTQ x BTK]
        for (int i = tid; i < BTQ * (BTK / 4); i += BNT) {
            int row = i >> 4, c = (i & 15) << 2;
            float rv = rinv_s[row];
            float4 p = *(const float4*)(eb + row * EBS + c);
            p.x *= rv; p.y *= rv; p.z *= rv; p.w *= rv;
            __stcs((float4*)(eg + (size_t)row * NS + vt * BTK + c), p);
        }
        __syncthreads();

        if (vt + 2 < BNTILES) {
            float* ed = ebuf + (vt & 1) * BTQ * EBS;
            float* vd = vbuf + (vt & 1) * BTK * VSS;
            for (int i = tid; i < BTQ * (BTK / 4); i += BNT) {
                int r = i >> 4, c = (i & 15) << 2;
                cp_async16(ed + r * EBS + c, eg + (size_t)r * NS + (vt + 2) * BTK + c);
            }
            for (int i = tid; i < BTK * 16; i += BNT) {
                int r = i >> 4, c = (i & 15) << 2;
                cp_async16(vd + r * VSS + c, vg + (size_t)((vt + 2) * BTK + r) * ND + c);
            }
            CP_COMMIT();
        }
    }

    // ---- reduce 4 k-partials via scratch (dead vbuf) ----
    {
        float* reg = scratch + (wk * BTQ) * PRS;
        #pragma unroll
        for (int nt = 0; nt < 8; nt++) {
            *(float2*)(reg + (wm * 16 + g) * PRS + nt * 8 + 2 * tg) = make_float2(acc[nt][0], acc[nt][1]);
            *(float2*)(reg + (wm * 16 + g + 8) * PRS + nt * 8 + 2 * tg) = make_float2(acc[nt][2], acc[nt][3]);
        }
    }
    __syncthreads();
    {
        int row = tid >> 3;            // 0..31
        int c8  = (tid & 7) << 3;      // 0..56
        float s[8];
        #pragma unroll
        for (int j = 0; j < 8; j++) s[j] = 0.0f;
        #pragma unroll
        for (int k = 0; k < 4; k++) {
            const float* p = scratch + (k * BTQ + row) * PRS + c8;
            #pragma unroll
            for (int j = 0; j < 8; j++) s[j] += p[j];
        }
        float rv = rinv_s[row];
        float4 o0 = make_float4(s[0] * rv, s[1] * rv, s[2] * rv, s[3] * rv);
        float4 o1 = make_float4(s[4] * rv, s[5] * rv, s[6] * rv, s[7] * rv);
        float* op = out + (bh * NS + (size_t)(q0 + row)) * ND + c8;
        *(float4*)op = o0;
        *(float4*)(op + 4) = o1;
    }
}

extern "C" void kernel_launch(void* const* d_in, const int* in_sizes, int n_in,
                              void* d_out, int out_size) {
    const float* q    = (const float*)d_in[0];
    const float* k    = (const float*)d_in[1];
    const float* v    = (const float*)d_in[2];
    const int*   mask = (const int*)  d_in[3];
    const float* adj  = (const float*)d_in[4];
    const float* dist = (const float*)d_in[5];

    float* out  = (float*)d_out;                      // [B,H,S,D]
    float* attn = out + (size_t)NB * NH * NS * ND;    // [B,H,S,S]

    prep_kernel<<<(NB * NS * NS) / 1024, 256>>>(dist, adj, mask);
    prep_qkv_kernel<<<(NB * NH * NS * ND) / 1024, 256>>>(q, k, v);

    const size_t smem_a = (size_t)(ATQ * QHS + 2 * ATK * KHS + 64) * sizeof(float);
    cudaFuncSetAttribute(score_kernel,
                         cudaFuncAttributeMaxDynamicSharedMemorySize, (int)smem_a);
    dim3 gridA(NS / ATQ, NH, NB);
    score_kernel<<<gridA, ANT, smem_a>>>(attn);

    const size_t smem_b = (size_t)(2 * BTQ * EBS + 2 * BTK * VSS + 32) * sizeof(float);
    cudaFuncSetAttribute(pv_kernel,
                         cudaFuncAttributeMaxDynamicSharedMemorySize, (int)smem_b);
    dim3 gridB(NS / BTQ, NH, NB);
    pv_kernel<<<gridB, BNT, smem_b>>>(out, attn);
}

// round 14
// speedup vs baseline: 1.2048x; 1.0638x over previous
#include <cuda_runtime.h>
#include <cuda_bf16.h>
#include <math.h>
#include <stdint.h>

#define NB 4
#define NH 16
#define NS 1024
#define ND 64

#define QHS 68      // q packed tile stride (words), mod 32 == 4
#define KHS 68      // k tile stride (words), mod 32 == 4
#define VSS 72      // v tile stride, mod 32 == 8
#define EBS 68      // e tile stride (kernel B), mod 32 == 4
#define PRS 66      // reduction scratch stride

// Kernel A geometry
#define ATQ 64
#define ATK 64
#define ANT 256
#define ANTILES (NS / ATK)

// Kernel B geometry
#define BTQ 32
#define BTK 64
#define BNT 256
#define BNTILES (NS / BTK)

// Precomputed, head-independent tables + scratch.
__device__ float    g_resc[NB * NS * NS];        // (1+e)/(1+exp(1-dist))
__device__ float    g_madj[NB * NS * NS];        // mask ? adj : -1e9
__device__ uint32_t g_qhl[NB * NH * NS * ND];    // q/8 packed bf16 hi|lo
__device__ uint32_t g_khl[NB * NH * NS * ND];    // k packed bf16 hi|lo
__device__ float    g_vtf[NB * NH * NS * ND];    // tf32(v) bits
__device__ float    g_rinv[NB * NH * NS];        // 1 / row sums

__device__ __forceinline__ uint32_t f2tf(float f) {
    uint32_t r;
    asm("cvt.rna.tf32.f32 %0, %1;" : "=r"(r) : "f"(f));
    return r;
}
__device__ __forceinline__ uint32_t pack_bf16x2_split(float f) {
    __nv_bfloat16 h = __float2bfloat16(f);
    float resid = f - __bfloat162float(h);
    __nv_bfloat16 l = __float2bfloat16(resid);
    return (uint32_t)__bfloat16_as_ushort(h) |
           ((uint32_t)__bfloat16_as_ushort(l) << 16);
}

#define PREP_TBL_BLOCKS ((NB * NS * NS) / 1024)          // 4096
#define PREP_QKV_BLOCKS ((NB * NH * NS * ND) / 1024)     // 4096

__global__ void prep_all_kernel(const float* __restrict__ dist,
                                const float* __restrict__ adj,
                                const int*   __restrict__ mask,
                                const float* __restrict__ q,
                                const float* __restrict__ k,
                                const float* __restrict__ v) {
    int bid = blockIdx.x;
    if (bid < PREP_TBL_BLOCKS) {
        int i = (bid * 256 + threadIdx.x) * 4;
        int b = i >> 20;
        int j = i & (NS - 1);
        float4 d = *(const float4*)(dist + i);
        float4 a = *(const float4*)(adj + i);
        int4   m = *(const int4*)(mask + b * NS + j);
        float4 r;
        r.x = 3.7182817f / (1.0f + __expf(1.0f - d.x));
        r.y = 3.7182817f / (1.0f + __expf(1.0f - d.y));
        r.z = 3.7182817f / (1.0f + __expf(1.0f - d.z));
        r.w = 3.7182817f / (1.0f + __expf(1.0f - d.w));
        *(float4*)(g_resc + i) = r;
        float4 ma;
        ma.x = (m.x == 0) ? -1.0e9f : a.x;
        ma.y = (m.y == 0) ? -1.0e9f : a.y;
        ma.z = (m.z == 0) ? -1.0e9f : a.z;
        ma.w = (m.w == 0) ? -1.0e9f : a.w;
        *(float4*)(g_madj + i) = ma;
    } else {
        int i = ((bid - PREP_TBL_BLOCKS) * 256 + threadIdx.x) * 4;
        float4 qv = *(const float4*)(q + i);
        float4 kv = *(const float4*)(k + i);
        float4 vv = *(const float4*)(v + i);
        uint4 qo, ko;
        float4 vo;
        qo.x = pack_bf16x2_split(qv.x * 0.125f);
        qo.y = pack_bf16x2_split(qv.y * 0.125f);
        qo.z = pack_bf16x2_split(qv.z * 0.125f);
        qo.w = pack_bf16x2_split(qv.w * 0.125f);
        ko.x = pack_bf16x2_split(kv.x);
        ko.y = pack_bf16x2_split(kv.y);
        ko.z = pack_bf16x2_split(kv.z);
        ko.w = pack_bf16x2_split(kv.w);
        vo.x = __uint_as_float(f2tf(vv.x));
        vo.y = __uint_as_float(f2tf(vv.y));
        vo.z = __uint_as_float(f2tf(vv.z));
        vo.w = __uint_as_float(f2tf(vv.w));
        *(uint4*)(g_qhl + i) = qo;
        *(uint4*)(g_khl + i) = ko;
        *(float4*)(g_vtf + i) = vo;
    }
}

__device__ __forceinline__ void mma_bf16(float* c,
                                         uint32_t a0, uint32_t a1, uint32_t a2, uint32_t a3,
                                         uint32_t b0, uint32_t b1) {
    asm volatile("mma.sync.aligned.m16n8k16.row.col.f32.bf16.bf16.f32 "
                 "{%0,%1,%2,%3}, {%4,%5,%6,%7}, {%8,%9}, {%0,%1,%2,%3};"
                 : "+f"(c[0]), "+f"(c[1]), "+f"(c[2]), "+f"(c[3])
                 : "r"(a0), "r"(a1), "r"(a2), "r"(a3), "r"(b0), "r"(b1));
}
__device__ __forceinline__ void mma_tf32(float* c,
                                         uint32_t a0, uint32_t a1, uint32_t a2, uint32_t a3,
                                         uint32_t b0, uint32_t b1) {
    asm volatile("mma.sync.aligned.m16n8k8.row.col.f32.tf32.tf32.f32 "
                 "{%0,%1,%2,%3}, {%4,%5,%6,%7}, {%8,%9}, {%0,%1,%2,%3};"
                 : "+f"(c[0]), "+f"(c[1]), "+f"(c[2]), "+f"(c[3])
                 : "r"(a0), "r"(a1), "r"(a2), "r"(a3), "r"(b0), "r"(b1));
}

__device__ __forceinline__ void cp_async16(void* smem_dst, const void* gsrc) {
    uint32_t sa = (uint32_t)__cvta_generic_to_shared(smem_dst);
    asm volatile("cp.async.cg.shared.global [%0], [%1], 16;" :: "r"(sa), "l"(gsrc));
}
#define CP_COMMIT()  asm volatile("cp.async.commit_group;")
#define CP_WAIT(n)   asm volatile("cp.async.wait_group %0;" :: "n"(n))

// ==== Kernel A: scores -> unnormalized e (tf32 bits), TQ=64, occ 2 ====
__global__ __launch_bounds__(ANT, 2)
void score_kernel(float* __restrict__ attn_out) {
    extern __shared__ float smem[];
    uint32_t* qhl_s = (uint32_t*)smem;                   // ATQ*QHS   (4352 w)
    uint32_t* kbuf  = (uint32_t*)(smem + ATQ * QHS);     // 2*ATK*KHS (8704 w)
    float*    rs_sm = smem + ATQ * QHS + 2 * ATK * KHS;  // 64

    const int tid  = threadIdx.x;
    const int wid  = tid >> 5;
    const int lane = tid & 31;
    const int g    = lane >> 2;
    const int tg   = lane & 3;
    const int wm   = wid >> 1;    // 0..3 (m16 group within TQ=64)
    const int wn   = wid & 1;     // 0..1 (n32 group within TK=64)

    const int q0 = blockIdx.x * ATQ;
    const int h  = blockIdx.y;
    const int b  = blockIdx.z;
    const size_t bh = (size_t)b * NH + h;

    const uint32_t* qg  = g_qhl + (bh * NS + q0) * ND;
    const uint32_t* khg = g_khl + bh * NS * ND;
    float* eg = attn_out + (bh * NS + q0) * NS;

    if (tid < 64) rs_sm[tid] = 0.0f;

    // ---- prologue: q + k0 (group 0), k1 (group 1) ----
    for (int i = tid; i < ATQ * 16; i += ANT) {
        int r = i >> 4, c = (i & 15) << 2;
        cp_async16(qhl_s + r * QHS + c, qg + (size_t)r * ND + c);
    }
    for (int i = tid; i < ATK * 16; i += ANT) {
        int r = i >> 4, c = (i & 15) << 2;
        cp_async16(kbuf + r * KHS + c, khg + (size_t)r * ND + c);
    }
    CP_COMMIT();
    for (int i = tid; i < ATK * 16; i += ANT) {
        int r = i >> 4, c = (i & 15) << 2;
        cp_async16(kbuf + ATK * KHS + r * KHS + c, khg + (size_t)(ATK + r) * ND + c);
    }
    CP_COMMIT();
    CP_WAIT(1);
    __syncthreads();

    // ---- A fragments (m16 slice of q) -> packed regs ----
    uint32_t apk[8][4];
    const int r_lo = wm * 16 + g;
    #pragma unroll
    for (int ks = 0; ks < 8; ks++) {
        int col = ks * 8 + tg;
        apk[ks][0] = qhl_s[r_lo * QHS + col];
        apk[ks][1] = qhl_s[(r_lo + 8) * QHS + col];
        apk[ks][2] = qhl_s[r_lo * QHS + col + 4];
        apk[ks][3] = qhl_s[(r_lo + 8) * QHS + col + 4];
    }

    float rs0 = 0.0f, rs1 = 0.0f;
    const float* rbase = g_resc + ((size_t)b * NS + q0 + r_lo) * NS;
    const float* abase = g_madj + ((size_t)b * NS + q0 + r_lo) * NS;

    for (int kt = 0; kt < ANTILES; kt++) {
        if (kt < ANTILES - 1) { CP_WAIT(1); } else { CP_WAIT(0); }
        __syncthreads();

        const uint32_t* kw = kbuf + (kt & 1) * ATK * KHS;

        float chh[4][4], cll[4][4];
        #pragma unroll
        for (int nt = 0; nt < 4; nt++)
            #pragma unroll
            for (int j = 0; j < 4; j++) { chh[nt][j] = 0.0f; cll[nt][j] = 0.0f; }

        #pragma unroll
        for (int ks = 0; ks < 8; ks++) {
            int col = ks * 8 + tg;
            uint32_t p0 = apk[ks][0], p1 = apk[ks][1];
            uint32_t p2 = apk[ks][2], p3 = apk[ks][3];
            uint32_t hh0 = __byte_perm(p0, p0, 0x1010);
            uint32_t hh1 = __byte_perm(p1, p1, 0x1010);
            uint32_t hh2 = __byte_perm(p2, p2, 0x1010);
            uint32_t hh3 = __byte_perm(p3, p3, 0x1010);
            uint32_t ll0 = __byte_perm(p0, p0, 0x3232);
            uint32_t ll1 = __byte_perm(p1, p1, 0x3232);
            uint32_t ll2 = __byte_perm(p2, p2, 0x3232);
            uint32_t ll3 = __byte_perm(p3, p3, 0x3232);
            #pragma unroll
            for (int nt = 0; nt < 4; nt++) {
                uint32_t bp0 = kw[(wn * 32 + nt * 8 + g) * KHS + col];
                uint32_t bp1 = kw[(wn * 32 + nt * 8 + g) * KHS + col + 4];
                mma_bf16(chh[nt], hh0, hh1, hh2, hh3, bp0, bp1);
                mma_bf16(cll[nt], ll0, ll1, ll2, ll3, bp0, bp1);
            }
        }

        // epilogue: e = exp(relu(s)*resc + madj); row sums; store tf32(e)
        #pragma unroll
        for (int nt = 0; nt < 4; nt++) {
            int kc = kt * ATK + wn * 32 + nt * 8 + 2 * tg;
            float2 rl = *(const float2*)(rbase + kc);
            float2 al = *(const float2*)(abase + kc);
            float2 rh = *(const float2*)(rbase + 8 * NS + kc);
            float2 ah = *(const float2*)(abase + 8 * NS + kc);
            float e00 = __expf(fmaxf(chh[nt][0] + cll[nt][0], 0.0f) * rl.x + al.x);
            float e01 = __expf(fmaxf(chh[nt][1] + cll[nt][1], 0.0f) * rl.y + al.y);
            float e10 = __expf(fmaxf(chh[nt][2] + cll[nt][2], 0.0f) * rh.x + ah.x);
            float e11 = __expf(fmaxf(chh[nt][3] + cll[nt][3], 0.0f) * rh.y + ah.y);
            rs0 += e00 + e01;
            rs1 += e10 + e11;
            float2 t0 = make_float2(__uint_as_float(f2tf(e00)), __uint_as_float(f2tf(e01)));
            float2 t1 = make_float2(__uint_as_float(f2tf(e10)), __uint_as_float(f2tf(e11)));
            __stcs((float2*)(eg + (size_t)r_lo * NS + kc), t0);
            __stcs((float2*)(eg + (size_t)(r_lo + 8) * NS + kc), t1);
        }
        __syncthreads();

        if (kt + 2 < ANTILES) {
            uint32_t* dst = kbuf + (kt & 1) * ATK * KHS;
            for (int i = tid; i < ATK * 16; i += ANT) {
                int r = i >> 4, c = (i & 15) << 2;
                cp_async16(dst + r * KHS + c,
                           khg + (size_t)((kt + 2) * ATK + r) * ND + c);
            }
            CP_COMMIT();
        }
    }

    // row sums -> g_rinv
    rs0 += __shfl_xor_sync(0xffffffffu, rs0, 1);
    rs0 += __shfl_xor_sync(0xffffffffu, rs0, 2);
    rs1 += __shfl_xor_sync(0xffffffffu, rs1, 1);
    rs1 += __shfl_xor_sync(0xffffffffu, rs1, 2);
    if (tg == 0) {
        atomicAdd(&rs_sm[r_lo], rs0);
        atomicAdd(&rs_sm[r_lo + 8], rs1);
    }
    __syncthreads();
    if (tid < 64) g_rinv[bh * NS + q0 + tid] = 1.0f / rs_sm[tid];
}

// ============ Kernel B: normalize attn in place + out = P @ V ============
__global__ __launch_bounds__(BNT, 3)
void pv_kernel(float* __restrict__ out,
               float* __restrict__ attn) {
    extern __shared__ float smem[];
    float* ebuf   = smem;                              // 2*BTQ*EBS (4352 w)
    float* vbuf   = ebuf + 2 * BTQ * EBS;              // 2*BTK*VSS (9216 w)
    float* rinv_s = vbuf + 2 * BTK * VSS;              // 32
    float* scratch = vbuf;                             // dead after tile loop

    const int tid  = threadIdx.x;
    const int wid  = tid >> 5;
    const int lane = tid & 31;
    const int g    = lane >> 2;
    const int tg   = lane & 3;
    const int wm   = wid >> 2;    // 0..1 (m16)
    const int wk   = wid & 3;     // 0..3 (k16 slice within BTK=64)

    const int q0 = blockIdx.x * BTQ;
    const int h  = blockIdx.y;
    const int b  = blockIdx.z;
    const size_t bh = (size_t)b * NH + h;

    float* eg = attn + (bh * NS + q0) * NS;
    const float* vg = g_vtf + bh * NS * ND;

    if (tid < 32) rinv_s[tid] = g_rinv[bh * NS + q0 + tid];

    // ---- prologue: tiles 0,1 (e + v), one cp group each ----
    for (int t = 0; t < 2; t++) {
        float* ed = ebuf + t * BTQ * EBS;
        float* vd = vbuf + t * BTK * VSS;
        for (int i = tid; i < BTQ * (BTK / 4); i += BNT) {
            int r = i >> 4, c = (i & 15) << 2;
            cp_async16(ed + r * EBS + c, eg + (size_t)r * NS + t * BTK + c);
        }
        for (int i = tid; i < BTK * 16; i += BNT) {
            int r = i >> 4, c = (i & 15) << 2;
            cp_async16(vd + r * VSS + c, vg + (size_t)(t * BTK + r) * ND + c);
        }
        CP_COMMIT();
    }
    CP_WAIT(1);
    __syncthreads();

    const int r_lo = wm * 16 + g;
    float acc[8][4];
    #pragma unroll
    for (int nt = 0; nt < 8; nt++)
        #pragma unroll
        for (int j = 0; j < 4; j++) acc[nt][j] = 0.0f;

    for (int vt = 0; vt < BNTILES; vt++) {
        if (vt < BNTILES - 1) { CP_WAIT(1); } else { CP_WAIT(0); }
        __syncthreads();

        const float* eb = ebuf + (vt & 1) * BTQ * EBS;
        const float* vb = vbuf + (vt & 1) * BTK * VSS;

        #pragma unroll
        for (int s = 0; s < 2; s++) {
            int kl = wk * 16 + s * 8;
            uint32_t a0 = __float_as_uint(eb[r_lo * EBS + kl + tg]);
            uint32_t a1 = __float_as_uint(eb[(r_lo + 8) * EBS + kl + tg]);
            uint32_t a2 = __float_as_uint(eb[r_lo * EBS + kl + tg + 4]);
            uint32_t a3 = __float_as_uint(eb[(r_lo + 8) * EBS + kl + tg + 4]);
            #pragma unroll
            for (int nt = 0; nt < 8; nt++) {
                uint32_t b0 = __float_as_uint(vb[(kl + tg) * VSS + nt * 8 + g]);
                uint32_t b1 = __float_as_uint(vb[(kl + tg + 4) * VSS + nt * 8 + g]);
                mma_tf32(acc[nt], a0, a1, a2, a3, b0, b1);
            }
        }

        // normalize + write back attn chunk [BTQ x BTK]
        for (int i = tid; i < BTQ * (BTK / 4); i += BNT) {
            int row = i >> 4, c = (i & 15) << 2;
            float rv = rinv_s[row];
            float4 p = *(const float4*)(eb + row * EBS + c);
            p.x *= rv; p.y *= rv; p.z *= rv; p.w *= rv;
            __stcs((float4*)(eg + (size_t)row * NS + vt * BTK + c), p);
        }
        __syncthreads();

        if (vt + 2 < BNTILES) {
            float* ed = ebuf + (vt & 1) * BTQ * EBS;
            float* vd = vbuf + (vt & 1) * BTK * VSS;
            for (int i = tid; i < BTQ * (BTK / 4); i += BNT) {
                int r = i >> 4, c = (i & 15) << 2;
                cp_async16(ed + r * EBS + c, eg + (size_t)r * NS + (vt + 2) * BTK + c);
            }
            for (int i = tid; i < BTK * 16; i += BNT) {
                int r = i >> 4, c = (i & 15) << 2;
                cp_async16(vd + r * VSS + c, vg + (size_t)((vt + 2) * BTK + r) * ND + c);
            }
            CP_COMMIT();
        }
    }

    // ---- reduce 4 k-partials via scratch (dead vbuf) ----
    {
        float* reg = scratch + (wk * BTQ) * PRS;
        #pragma unroll
        for (int nt = 0; nt < 8; nt++) {
            *(float2*)(reg + (wm * 16 + g) * PRS + nt * 8 + 2 * tg) = make_float2(acc[nt][0], acc[nt][1]);
            *(float2*)(reg + (wm * 16 + g + 8) * PRS + nt * 8 + 2 * tg) = make_float2(acc[nt][2], acc[nt][3]);
        }
    }
    __syncthreads();
    {
        int row = tid >> 3;            // 0..31
        int c8  = (tid & 7) << 3;      // 0..56
        float s[8];
        #pragma unroll
        for (int j = 0; j < 8; j++) s[j] = 0.0f;
        #pragma unroll
        for (int k = 0; k < 4; k++) {
            const float* p = scratch + (k * BTQ + row) * PRS + c8;
            #pragma unroll
            for (int j = 0; j < 8; j++) s[j] += p[j];
        }
        float rv = rinv_s[row];
        float4 o0 = make_float4(s[0] * rv, s[1] * rv, s[2] * rv, s[3] * rv);
        float4 o1 = make_float4(s[4] * rv, s[5] * rv, s[6] * rv, s[7] * rv);
        float* op = out + (bh * NS + (size_t)(q0 + row)) * ND + c8;
        *(float4*)op = o0;
        *(float4*)(op + 4) = o1;
    }
}

extern "C" void kernel_launch(void* const* d_in, const int* in_sizes, int n_in,
                              void* d_out, int out_size) {
    const float* q    = (const float*)d_in[0];
    const float* k    = (const float*)d_in[1];
    const float* v    = (const float*)d_in[2];
    const int*   mask = (const int*)  d_in[3];
    const float* adj  = (const float*)d_in[4];
    const float* dist = (const float*)d_in[5];

    float* out  = (float*)d_out;                      // [B,H,S,D]
    float* attn = out + (size_t)NB * NH * NS * ND;    // [B,H,S,S]

    prep_all_kernel<<<PREP_TBL_BLOCKS + PREP_QKV_BLOCKS, 256>>>(dist, adj, mask, q, k, v);

    const size_t smem_a = (size_t)(ATQ * QHS + 2 * ATK * KHS + 64) * sizeof(float);
    cudaFuncSetAttribute(score_kernel,
                         cudaFuncAttributeMaxDynamicSharedMemorySize, (int)smem_a);
    dim3 gridA(NS / ATQ, NH, NB);
    score_kernel<<<gridA, ANT, smem_a>>>(attn);

    const size_t smem_b = (size_t)(2 * BTQ * EBS + 2 * BTK * VSS + 32) * sizeof(float);
    cudaFuncSetAttribute(pv_kernel,
                         cudaFuncAttributeMaxDynamicSharedMemorySize, (int)smem_b);
    dim3 gridB(NS / BTQ, NH, NB);
    pv_kernel<<<gridB, BNT, smem_b>>>(out, attn);
}

// round 16
// speedup vs baseline: 1.2750x; 1.0582x over previous
#include <cuda_runtime.h>
#include <cuda_bf16.h>
#include <math.h>
#include <stdint.h>

#define NB 4
#define NH 16
#define NS 1024
#define ND 64

#define QHS 68      // q packed tile stride (words), mod 32 == 4
#define KHS 68      // k tile stride (words), mod 32 == 4
#define VSS 72      // v tile stride, mod 32 == 8
#define EBS 68      // e tile stride (kernel B), mod 32 == 4
#define PRS 68      // reduction scratch stride (272B/row -> float4-aligned)

// Kernel A geometry
#define ATQ 128
#define ATK 64
#define ANT 256
#define ANTILES (NS / ATK)

// Kernel B geometry
#define BTQ 64
#define BTK 64
#define BNT 256
#define BNTILES (NS / BTK)

// Precomputed, head-independent tables + scratch.
__device__ float    g_resc[NB * NS * NS];        // (1+e)/(1+exp(1-dist))
__device__ float    g_madj[NB * NS * NS];        // mask ? adj : -1e9
__device__ uint32_t g_qhl[NB * NH * NS * ND];    // q/8 packed bf16 hi|lo
__device__ uint32_t g_khl[NB * NH * NS * ND];    // k packed bf16 hi|lo
__device__ float    g_vtf[NB * NH * NS * ND];    // tf32(v) bits
__device__ float    g_rinv[NB * NH * NS];        // 1 / row sums

__device__ __forceinline__ uint32_t f2tf(float f) {
    uint32_t r;
    asm("cvt.rna.tf32.f32 %0, %1;" : "=r"(r) : "f"(f));
    return r;
}
__device__ __forceinline__ uint32_t pack_bf16x2_split(float f) {
    __nv_bfloat16 h = __float2bfloat16(f);
    float resid = f - __bfloat162float(h);
    __nv_bfloat16 l = __float2bfloat16(resid);
    return (uint32_t)__bfloat16_as_ushort(h) |
           ((uint32_t)__bfloat16_as_ushort(l) << 16);
}

#define PREP_TBL_BLOCKS ((NB * NS * NS) / 1024)          // 4096
#define PREP_QKV_BLOCKS ((NB * NH * NS * ND) / 1024)     // 4096

__global__ void prep_all_kernel(const float* __restrict__ dist,
                                const float* __restrict__ adj,
                                const int*   __restrict__ mask,
                                const float* __restrict__ q,
                                const float* __restrict__ k,
                                const float* __restrict__ v) {
    int bid = blockIdx.x;
    if (bid < PREP_TBL_BLOCKS) {
        int i = (bid * 256 + threadIdx.x) * 4;
        int b = i >> 20;
        int j = i & (NS - 1);
        float4 d = *(const float4*)(dist + i);
        float4 a = *(const float4*)(adj + i);
        int4   m = *(const int4*)(mask + b * NS + j);
        float4 r;
        r.x = 3.7182817f / (1.0f + __expf(1.0f - d.x));
        r.y = 3.7182817f / (1.0f + __expf(1.0f - d.y));
        r.z = 3.7182817f / (1.0f + __expf(1.0f - d.z));
        r.w = 3.7182817f / (1.0f + __expf(1.0f - d.w));
        *(float4*)(g_resc + i) = r;
        float4 ma;
        ma.x = (m.x == 0) ? -1.0e9f : a.x;
        ma.y = (m.y == 0) ? -1.0e9f : a.y;
        ma.z = (m.z == 0) ? -1.0e9f : a.z;
        ma.w = (m.w == 0) ? -1.0e9f : a.w;
        *(float4*)(g_madj + i) = ma;
    } else {
        int i = ((bid - PREP_TBL_BLOCKS) * 256 + threadIdx.x) * 4;
        float4 qv = *(const float4*)(q + i);
        float4 kv = *(const float4*)(k + i);
        float4 vv = *(const float4*)(v + i);
        uint4 qo, ko;
        float4 vo;
        qo.x = pack_bf16x2_split(qv.x * 0.125f);
        qo.y = pack_bf16x2_split(qv.y * 0.125f);
        qo.z = pack_bf16x2_split(qv.z * 0.125f);
        qo.w = pack_bf16x2_split(qv.w * 0.125f);
        ko.x = pack_bf16x2_split(kv.x);
        ko.y = pack_bf16x2_split(kv.y);
        ko.z = pack_bf16x2_split(kv.z);
        ko.w = pack_bf16x2_split(kv.w);
        vo.x = __uint_as_float(f2tf(vv.x));
        vo.y = __uint_as_float(f2tf(vv.y));
        vo.z = __uint_as_float(f2tf(vv.z));
        vo.w = __uint_as_float(f2tf(vv.w));
        *(uint4*)(g_qhl + i) = qo;
        *(uint4*)(g_khl + i) = ko;
        *(float4*)(g_vtf + i) = vo;
    }
}

__device__ __forceinline__ void mma_bf16(float* c,
                                         uint32_t a0, uint32_t a1, uint32_t a2, uint32_t a3,
                                         uint32_t b0, uint32_t b1) {
    asm volatile("mma.sync.aligned.m16n8k16.row.col.f32.bf16.bf16.f32 "
                 "{%0,%1,%2,%3}, {%4,%5,%6,%7}, {%8,%9}, {%0,%1,%2,%3};"
                 : "+f"(c[0]), "+f"(c[1]), "+f"(c[2]), "+f"(c[3])
                 : "r"(a0), "r"(a1), "r"(a2), "r"(a3), "r"(b0), "r"(b1));
}
__device__ __forceinline__ void mma_tf32(float* c,
                                         uint32_t a0, uint32_t a1, uint32_t a2, uint32_t a3,
                                         uint32_t b0, uint32_t b1) {
    asm volatile("mma.sync.aligned.m16n8k8.row.col.f32.tf32.tf32.f32 "
                 "{%0,%1,%2,%3}, {%4,%5,%6,%7}, {%8,%9}, {%0,%1,%2,%3};"
                 : "+f"(c[0]), "+f"(c[1]), "+f"(c[2]), "+f"(c[3])
                 : "r"(a0), "r"(a1), "r"(a2), "r"(a3), "r"(b0), "r"(b1));
}

__device__ __forceinline__ void cp_async16(void* smem_dst, const void* gsrc) {
    uint32_t sa = (uint32_t)__cvta_generic_to_shared(smem_dst);
    asm volatile("cp.async.cg.shared.global [%0], [%1], 16;" :: "r"(sa), "l"(gsrc));
}
#define CP_COMMIT()  asm volatile("cp.async.commit_group;")
#define CP_WAIT(n)   asm volatile("cp.async.wait_group %0;" :: "n"(n))

// ==== Kernel A: scores -> unnormalized e (tf32 bits), TQ=128, occ 2 ====
__global__ __launch_bounds__(ANT, 2)
void score_kernel(float* __restrict__ attn_out) {
    extern __shared__ float smem[];
    uint32_t* qhl_s = (uint32_t*)smem;                   // ATQ*QHS   (8704 w)
    uint32_t* kbuf  = (uint32_t*)(smem + ATQ * QHS);     // 2*ATK*KHS (8704 w)

    const int tid  = threadIdx.x;
    const int wid  = tid >> 5;    // 0..7 (m16 group within TQ=128)
    const int lane = tid & 31;
    const int g    = lane >> 2;
    const int tg   = lane & 3;

    const int q0 = blockIdx.x * ATQ;
    const int h  = blockIdx.y;
    const int b  = blockIdx.z;
    const size_t bh = (size_t)b * NH + h;

    const uint32_t* qg  = g_qhl + (bh * NS + q0) * ND;
    const uint32_t* khg = g_khl + bh * NS * ND;
    float* eg = attn_out + (bh * NS + q0) * NS;

    // ---- prologue: q + k0 (group 0), k1 (group 1) ----
    for (int i = tid; i < ATQ * 16; i += ANT) {
        int r = i >> 4, c = (i & 15) << 2;
        cp_async16(qhl_s + r * QHS + c, qg + (size_t)r * ND + c);
    }
    for (int i = tid; i < ATK * 16; i += ANT) {
        int r = i >> 4, c = (i & 15) << 2;
        cp_async16(kbuf + r * KHS + c, khg + (size_t)r * ND + c);
    }
    CP_COMMIT();
    for (int i = tid; i < ATK * 16; i += ANT) {
        int r = i >> 4, c = (i & 15) << 2;
        cp_async16(kbuf + ATK * KHS + r * KHS + c, khg + (size_t)(ATK + r) * ND + c);
    }
    CP_COMMIT();
    CP_WAIT(1);
    __syncthreads();

    // ---- A fragments (m16 slice of q) -> packed regs ----
    uint32_t apk[8][4];
    const int r_lo = wid * 16 + g;
    #pragma unroll
    for (int ks = 0; ks < 8; ks++) {
        int col = ks * 8 + tg;
        apk[ks][0] = qhl_s[r_lo * QHS + col];
        apk[ks][1] = qhl_s[(r_lo + 8) * QHS + col];
        apk[ks][2] = qhl_s[r_lo * QHS + col + 4];
        apk[ks][3] = qhl_s[(r_lo + 8) * QHS + col + 4];
    }

    float rs0 = 0.0f, rs1 = 0.0f;
    const float* rbase = g_resc + ((size_t)b * NS + q0 + r_lo) * NS;
    const float* abase = g_madj + ((size_t)b * NS + q0 + r_lo) * NS;

    for (int kt = 0; kt < ANTILES; kt++) {
        if (kt < ANTILES - 1) { CP_WAIT(1); } else { CP_WAIT(0); }
        __syncthreads();

        const uint32_t* kw = kbuf + (kt & 1) * ATK * KHS;

        float c4[8][4];
        #pragma unroll
        for (int nt = 0; nt < 8; nt++)
            #pragma unroll
            for (int j = 0; j < 4; j++) c4[nt][j] = 0.0f;

        #pragma unroll
        for (int ks = 0; ks < 8; ks++) {
            int col = ks * 8 + tg;
            uint32_t p0 = apk[ks][0], p1 = apk[ks][1];
            uint32_t p2 = apk[ks][2], p3 = apk[ks][3];
            uint32_t hh0 = __byte_perm(p0, p0, 0x1010);
            uint32_t hh1 = __byte_perm(p1, p1, 0x1010);
            uint32_t hh2 = __byte_perm(p2, p2, 0x1010);
            uint32_t hh3 = __byte_perm(p3, p3, 0x1010);
            uint32_t ll0 = __byte_perm(p0, p0, 0x3232);
            uint32_t ll1 = __byte_perm(p1, p1, 0x3232);
            uint32_t ll2 = __byte_perm(p2, p2, 0x3232);
            uint32_t ll3 = __byte_perm(p3, p3, 0x3232);
            #pragma unroll
            for (int nt = 0; nt < 8; nt++) {
                uint32_t bp0 = kw[(nt * 8 + g) * KHS + col];
                uint32_t bp1 = kw[(nt * 8 + g) * KHS + col + 4];
                mma_bf16(c4[nt], hh0, hh1, hh2, hh3, bp0, bp1);
                mma_bf16(c4[nt], ll0, ll1, ll2, ll3, bp0, bp1);
            }
        }

        // epilogue: e = exp(relu(s)*resc + madj); row sums; store tf32(e)
        #pragma unroll
        for (int nt = 0; nt < 8; nt++) {
            int kc = kt * ATK + nt * 8 + 2 * tg;
            float2 rl = *(const float2*)(rbase + kc);
            float2 al = *(const float2*)(abase + kc);
            float2 rh = *(const float2*)(rbase + 8 * NS + kc);
            float2 ah = *(const float2*)(abase + 8 * NS + kc);
            float e00 = __expf(fmaxf(c4[nt][0], 0.0f) * rl.x + al.x);
            float e01 = __expf(fmaxf(c4[nt][1], 0.0f) * rl.y + al.y);
            float e10 = __expf(fmaxf(c4[nt][2], 0.0f) * rh.x + ah.x);
            float e11 = __expf(fmaxf(c4[nt][3], 0.0f) * rh.y + ah.y);
            rs0 += e00 + e01;
            rs1 += e10 + e11;
            float2 t0 = make_float2(__uint_as_float(f2tf(e00)), __uint_as_float(f2tf(e01)));
            float2 t1 = make_float2(__uint_as_float(f2tf(e10)), __uint_as_float(f2tf(e11)));
            __stcs((float2*)(eg + (size_t)r_lo * NS + kc), t0);
            __stcs((float2*)(eg + (size_t)(r_lo + 8) * NS + kc), t1);
        }
        __syncthreads();

        if (kt + 2 < ANTILES) {
            uint32_t* dst = kbuf + (kt & 1) * ATK * KHS;
            for (int i = tid; i < ATK * 16; i += ANT) {
                int r = i >> 4, c = (i & 15) << 2;
                cp_async16(dst + r * KHS + c,
                           khg + (size_t)((kt + 2) * ATK + r) * ND + c);
            }
            CP_COMMIT();
        }
    }

    // row sums: each warp owns its full rows -> quad reduce, direct store
    rs0 += __shfl_xor_sync(0xffffffffu, rs0, 1);
    rs0 += __shfl_xor_sync(0xffffffffu, rs0, 2);
    rs1 += __shfl_xor_sync(0xffffffffu, rs1, 1);
    rs1 += __shfl_xor_sync(0xffffffffu, rs1, 2);
    if (tg == 0) {
        g_rinv[bh * NS + q0 + r_lo] = 1.0f / rs0;
        g_rinv[bh * NS + q0 + r_lo + 8] = 1.0f / rs1;
    }
}

// ============ Kernel B: normalize attn in place + out = P @ V, TQ=64 ============
__global__ __launch_bounds__(BNT, 3)
void pv_kernel(float* __restrict__ out,
               float* __restrict__ attn) {
    extern __shared__ float smem[];
    float* ebuf   = smem;                              // 2*BTQ*EBS (8704 w)
    float* vbuf   = ebuf + 2 * BTQ * EBS;              // 2*BTK*VSS (9216 w)
    float* rinv_s = vbuf + 2 * BTK * VSS;              // 64
    float* scratch = vbuf;                             // dead after tile loop (needs 2*BTQ*PRS = 8704 w)

    const int tid  = threadIdx.x;
    const int wid  = tid >> 5;
    const int lane = tid & 31;
    const int g    = lane >> 2;
    const int tg   = lane & 3;
    const int wm   = wid >> 1;    // 0..3 (m16 within TQ=64)
    const int wk   = wid & 1;     // 0..1 (k32 slice within BTK=64)

    const int q0 = blockIdx.x * BTQ;
    const int h  = blockIdx.y;
    const int b  = blockIdx.z;
    const size_t bh = (size_t)b * NH + h;

    float* eg = attn + (bh * NS + q0) * NS;
    const float* vg = g_vtf + bh * NS * ND;

    if (tid < 64) rinv_s[tid] = g_rinv[bh * NS + q0 + tid];

    // ---- prologue: tiles 0,1 (e + v), one cp group each ----
    for (int t = 0; t < 2; t++) {
        float* ed = ebuf + t * BTQ * EBS;
        float* vd = vbuf + t * BTK * VSS;
        for (int i = tid; i < BTQ * (BTK / 4); i += BNT) {
            int r = i >> 4, c = (i & 15) << 2;
            cp_async16(ed + r * EBS + c, eg + (size_t)r * NS + t * BTK + c);
        }
        for (int i = tid; i < BTK * 16; i += BNT) {
            int r = i >> 4, c = (i & 15) << 2;
            cp_async16(vd + r * VSS + c, vg + (size_t)(t * BTK + r) * ND + c);
        }
        CP_COMMIT();
    }
    CP_WAIT(1);
    __syncthreads();

    const int r_lo = wm * 16 + g;
    float acc[8][4];
    #pragma unroll
    for (int nt = 0; nt < 8; nt++)
        #pragma unroll
        for (int j = 0; j < 4; j++) acc[nt][j] = 0.0f;

    for (int vt = 0; vt < BNTILES; vt++) {
        if (vt < BNTILES - 1) { CP_WAIT(1); } else { CP_WAIT(0); }
        __syncthreads();

        const float* eb = ebuf + (vt & 1) * BTQ * EBS;
        const float* vb = vbuf + (vt & 1) * BTK * VSS;

        #pragma unroll
        for (int s = 0; s < 4; s++) {
            int kl = wk * 32 + s * 8;
            uint32_t a0 = __float_as_uint(eb[r_lo * EBS + kl + tg]);
            uint32_t a1 = __float_as_uint(eb[(r_lo + 8) * EBS + kl + tg]);
            uint32_t a2 = __float_as_uint(eb[r_lo * EBS + kl + tg + 4]);
            uint32_t a3 = __float_as_uint(eb[(r_lo + 8) * EBS + kl + tg + 4]);
            #pragma unroll
            for (int nt = 0; nt < 8; nt++) {
                uint32_t b0 = __float_as_uint(vb[(kl + tg) * VSS + nt * 8 + g]);
                uint32_t b1 = __float_as_uint(vb[(kl + tg + 4) * VSS + nt * 8 + g]);
                mma_tf32(acc[nt], a0, a1, a2, a3, b0, b1);
            }
        }

        // normalize + write back attn chunk [BTQ x BTK]
        for (int i = tid; i < BTQ * (BTK / 4); i += BNT) {
            int row = i >> 4, c = (i & 15) << 2;
            float rv = rinv_s[row];
            float4 p = *(const float4*)(eb + row * EBS + c);
            p.x *= rv; p.y *= rv; p.z *= rv; p.w *= rv;
            __stcs((float4*)(eg + (size_t)row * NS + vt * BTK + c), p);
        }
        __syncthreads();

        if (vt + 2 < BNTILES) {
            float* ed = ebuf + (vt & 1) * BTQ * EBS;
            float* vd = vbuf + (vt & 1) * BTK * VSS;
            for (int i = tid; i < BTQ * (BTK / 4); i += BNT) {
                int r = i >> 4, c = (i & 15) << 2;
                cp_async16(ed + r * EBS + c, eg + (size_t)r * NS + (vt + 2) * BTK + c);
            }
            for (int i = tid; i < BTK * 16; i += BNT) {
                int r = i >> 4, c = (i & 15) << 2;
                cp_async16(vd + r * VSS + c, vg + (size_t)((vt + 2) * BTK + r) * ND + c);
            }
            CP_COMMIT();
        }
    }

    // ---- reduce 2 k-partials via scratch (dead vbuf) ----
    {
        float* reg = scratch + (wk * BTQ) * PRS;
        #pragma unroll
        for (int nt = 0; nt < 8; nt++) {
            *(float2*)(reg + (wm * 16 + g) * PRS + nt * 8 + 2 * tg) = make_float2(acc[nt][0], acc[nt][1]);
            *(float2*)(reg + (wm * 16 + g + 8) * PRS + nt * 8 + 2 * tg) = make_float2(acc[nt][2], acc[nt][3]);
        }
    }
    __syncthreads();
    {
        int row = tid >> 2;            // 0..63
        int c16 = (tid & 3) << 4;      // 0, 16, 32, 48
        float rv = rinv_s[row];
        #pragma unroll
        for (int cc = 0; cc < 16; cc += 4) {
            int c4 = c16 + cc;
            float4 s0 = *(const float4*)(scratch + row * PRS + c4);
            float4 s1 = *(const float4*)(scratch + (BTQ + row) * PRS + c4);
            float4 o;
            o.x = (s0.x + s1.x) * rv;
            o.y = (s0.y + s1.y) * rv;
            o.z = (s0.z + s1.z) * rv;
            o.w = (s0.w + s1.w) * rv;
            *(float4*)(out + (bh * NS + (size_t)(q0 + row)) * ND + c4) = o;
        }
    }
}

extern "C" void kernel_launch(void* const* d_in, const int* in_sizes, int n_in,
                              void* d_out, int out_size) {
    const float* q    = (const float*)d_in[0];
    const float* k    = (const float*)d_in[1];
    const float* v    = (const float*)d_in[2];
    const int*   mask = (const int*)  d_in[3];
    const float* adj  = (const float*)d_in[4];
    const float* dist = (const float*)d_in[5];

    float* out  = (float*)d_out;                      // [B,H,S,D]
    float* attn = out + (size_t)NB * NH * NS * ND;    // [B,H,S,S]

    prep_all_kernel<<<PREP_TBL_BLOCKS + PREP_QKV_BLOCKS, 256>>>(dist, adj, mask, q, k, v);

    const size_t smem_a = (size_t)(ATQ * QHS + 2 * ATK * KHS) * sizeof(float);
    cudaFuncSetAttribute(score_kernel,
                         cudaFuncAttributeMaxDynamicSharedMemorySize, (int)smem_a);
    dim3 gridA(NS / ATQ, NH, NB);
    score_kernel<<<gridA, ANT, smem_a>>>(attn);

    const size_t smem_b = (size_t)(2 * BTQ * EBS + 2 * BTK * VSS + 64) * sizeof(float);
    cudaFuncSetAttribute(pv_kernel,
                         cudaFuncAttributeMaxDynamicSharedMemorySize, (int)smem_b);
    dim3 gridB(NS / BTQ, NH, NB);
    pv_kernel<<<gridB, BNT, smem_b>>>(out, attn);
}